// round 13
// baseline (speedup 1.0000x reference)
#include <cuda_runtime.h>
#include <cuda_fp16.h>
#include <cstdint>

#define NT 512
#define NODES 64
#define AR 2064
// smem byte offsets
#define SX    0
#define SA    16384
#define SB0   148480
#define SB2A  157440
#define SB2B  162304
#define SB1   167168
#define SLUT  179456
#define SG    180000
#define SMEM_BYTES 213792
#define WT_BYTES 31520

__device__ __align__(16) char g_Wt[WT_BYTES];

__device__ __forceinline__ void decode_pair(int p, int& u, int& v) {
    int uu = 0, r = p;
    while (r >= 16 - uu) { r -= 16 - uu; ++uu; }
    u = uu; v = uu + r;
}

// padded-row weight layout: B0 rows 280 halves (560B), B2 rows 152 halves (304B), B1 rows 24 halves (48B)
__global__ void prep_kernel(const float* __restrict__ w000, const float* __restrict__ w101,
                            const float* __restrict__ w110, const float* __restrict__ w112) {
    const float A000  = 0.044194173824159216f;
    const float A110  = 0.025515518153991442f;
    const float A101  = 0.0625f;
    const int tid = blockIdx.x * blockDim.x + threadIdx.x;
    const int nth = gridDim.x * blockDim.x;
    half* B0  = (half*)g_Wt;                 // 16 x 280
    half* B2A = (half*)(g_Wt + 8960);        // 16 x 152
    half* B2B = (half*)(g_Wt + 13824);       // 16 x 152
    half* B1  = (half*)(g_Wt + 18688);       // 256 x 24
    unsigned* LUT = (unsigned*)(g_Wt + 30976);

    for (int idx = tid; idx < 16 * 272; idx += nth) {
        int w = idx / 272, c = idx % 272;
        int p = (c < 136) ? c : c - 136;
        int u, v; decode_pair(p, u, v);
        const float* src = (c < 136) ? w000 : w110;
        float sc = (c < 136) ? A000 : A110;
        float cc = src[u * 256 + v * 16 + w];
        if (u != v) cc += src[v * 256 + u * 16 + w];
        B0[w * 280 + c] = __float2half_rn(cc * sc);
    }
    for (int idx = tid; idx < 16 * 144; idx += nth) {
        int w = idx / 144, p = idx % 144;
        float cc = 0.f;
        if (p < 136) {
            int u, v; decode_pair(p, u, v);
            cc = w112[u * 256 + v * 16 + w];
            if (u != v) cc += w112[v * 256 + u * 16 + w];
        }
        B2A[w * 152 + p] = __float2half_rn(cc * A000);  // A112/sqrt(10) == A000
        B2B[w * 152 + p] = __float2half_rn(cc * A110);  // A112/sqrt(30) == A110
    }
    for (int idx = tid; idx < 256 * 24; idx += nth) {
        int n = idx / 24, kk = idx % 24;
        int u = n >> 4, w = n & 15;
        float val = (kk < 16) ? w101[u * 256 + kk * 16 + w] * A101 : 0.f;
        B1[idx] = __float2half_rn(val);
    }
    for (int p = tid; p < 136; p += nth) {
        int u, v; decode_pair(p, u, v);
        LUT[p] = (unsigned)u | ((unsigned)v << 8);
    }
}

#define MMA(c, a, b) asm volatile( \
    "mma.sync.aligned.m16n8k16.row.col.f32.f16.f16.f32 " \
    "{%0,%1,%2,%3}, {%4,%5,%6,%7}, {%8,%9}, {%0,%1,%2,%3};" \
    : "+f"(c[0]), "+f"(c[1]), "+f"(c[2]), "+f"(c[3]) \
    : "r"(a[0]), "r"(a[1]), "r"(a[2]), "r"(a[3]), "r"(b[0]), "r"(b[1]))

#define LDSM4(a, addr) asm volatile( \
    "ldmatrix.sync.aligned.m8n8.x4.shared.b16 {%0,%1,%2,%3}, [%4];" \
    : "=r"(a[0]), "=r"(a[1]), "=r"(a[2]), "=r"(a[3]) : "r"(addr))

__global__ void __launch_bounds__(NT)
tsq_kernel(const float* __restrict__ nf, const float* __restrict__ nm,
           float* __restrict__ out, int nnodes) {
    extern __shared__ char sm[];
    const int t = threadIdx.x;
    const int nodeBase = blockIdx.x * NODES;

    // stage weights/LUT (g_Wt -> SB0.. contiguous)
    {
        const uint4* src = (const uint4*)g_Wt;
        uint4* dst = (uint4*)(sm + SB0);
        for (int i = t; i < WT_BYTES / 16; i += NT) dst[i] = src[i];
    }
    // stage x = nf+nm into float4 sX[node][u] = {x0[u], x1[u][0..2]}
    {
        const float4* a4 = (const float4*)nf;
        const float4* b4 = (const float4*)nm;
        float* sx = (float*)(sm + SX);
        const int limit = nnodes * 16;
        for (int i = t; i < NODES * 16; i += NT) {
            int gi = nodeBase * 16 + i;
            float4 a = make_float4(0.f, 0.f, 0.f, 0.f), b = a;
            if (gi < limit) { a = a4[gi]; b = b4[gi]; }
            int node = i >> 4, c0 = (i & 15) << 2;
            float vals[4] = {a.x + b.x, a.y + b.y, a.z + b.z, a.w + b.w};
#pragma unroll
            for (int j = 0; j < 4; ++j) {
                int c = c0 + j, u, f;
                if (c < 16) { u = c; f = 0; }
                else { u = (c - 16) / 3; f = 1 + (c - 16) % 3; }
                sx[(node * 16 + u) * 4 + f] = vals[j];
            }
        }
    }
    __syncthreads();

    // ---- basis: 8 threads/node, each 17 pairs; zero only the 5 K-pad gaps ----
    {
        const int node = t >> 3, q = t & 7;
        const float4* xr = (const float4*)(sm + SX) + node * 16;
        half* arow = (half*)(sm + SA + (size_t)node * AR);
        const unsigned* lut = (const unsigned*)(sm + SLUT);
        if (q < 5) {
            uint4 z = make_uint4(0, 0, 0, 0);
            *(uint4*)(arow + 408 + 144 * q) = z;   // cols 408+144q .. +7 (t_k K-pads)
        }
        for (int p = q; p < 136; p += 8) {
            unsigned uv = lut[p];
            float4 a = xr[uv & 255], b = xr[uv >> 8];
            float y   = a.x * b.x;
            float m00 = a.y * b.y, m01 = a.y * b.z, m02 = a.y * b.w;
            float m10 = a.z * b.y, m11 = a.z * b.z, m12 = a.z * b.w;
            float m20 = a.w * b.y, m21 = a.w * b.z, m22 = a.w * b.w;
            float h = m00 + m11;
            arow[p]       = __float2half_rn(y);
            arow[136 + p] = __float2half_rn(h + m22);
            arow[272 + p] = __float2half_rn(m01 + m10);
            arow[416 + p] = __float2half_rn(m02 + m20);
            arow[560 + p] = __float2half_rn(m12 + m21);
            arow[704 + p] = __float2half_rn(m00 - m11);
            arow[848 + p] = __float2half_rn(fmaf(2.f, m22, -h));
        }
        for (int u = q; u < 16; u += 8) arow[992 + u] = __float2half_rn(xr[u].x);
    }
    __syncthreads();

    // ---- MMA phase: 16 warps = mr(4) x sel(4); A via ldmatrix.x4, both n-halves per warp ----
    {
        const int w = t >> 5, lane = t & 31;
        const int mr = (w & 3) * 16, sel = w >> 2;
        const int r0 = lane >> 2, c2 = (lane & 3) * 2;
        // ldmatrix.x4 lane address: rows mr + (lane&7) + (lane&8), col-block +16B for lanes 16..31
        const char* lrow = sm + SA + (size_t)(mr + (lane & 7) + (lane & 8)) * AR
                         + ((lane >> 4) & 1) * 16;
        const unsigned lbase = (unsigned)__cvta_generic_to_shared(lrow);
        unsigned a[4], b[2];

        if (sel == 0) {
            // G = x0 * B1^T : K=16 (A cols 992..1007 -> byte 1984), all 32 n-tiles
            LDSM4(a, lbase + 1984);
            for (int j = 0; j < 32; ++j) {
                const char* bb = sm + SB1 + (size_t)(j * 8 + r0) * 48 + c2 * 2;
                b[0] = *(const unsigned*)bb;
                b[1] = *(const unsigned*)(bb + 16);
                float c[4] = {0.f, 0.f, 0.f, 0.f};
                MMA(c, a, b);
                int ncol = j * 8 + c2;
                *(half2*)(sm + SG + (size_t)(mr + r0) * 528 + ncol * 2) =
                    __floats2half2_rn(c[0], c[1]);
                *(half2*)(sm + SG + (size_t)(mr + r0 + 8) * 528 + ncol * 2) =
                    __floats2half2_rn(c[2], c[3]);
            }
            // out2 k=4, nh=0
            float c[4] = {0.f, 0.f, 0.f, 0.f};
            for (int ks = 0; ks < 9; ++ks) {
                LDSM4(a, lbase + 1696 + ks * 32);
                const char* bb = sm + SB2B + (size_t)r0 * 304 + ks * 32 + c2 * 2;
                b[0] = *(const unsigned*)bb;
                b[1] = *(const unsigned*)(bb + 16);
                MMA(c, a, b);
            }
            float* d = out + (size_t)(nodeBase + mr + r0) * 144 + 64 + 5 * c2 + 4;
            d[0] = c[0]; d[5] = c[1];
            float* d2 = d + (size_t)8 * 144;
            d2[0] = c[2]; d2[5] = c[3];
        } else if (sel == 1) {
            // out0 = [y|s] * B0^T : K=272, both n-halves
            float c0[4] = {0.f, 0.f, 0.f, 0.f}, c1[4] = {0.f, 0.f, 0.f, 0.f};
            for (int ks = 0; ks < 17; ++ks) {
                LDSM4(a, lbase + ks * 32);
                const char* bb = sm + SB0 + (size_t)r0 * 560 + ks * 32 + c2 * 2;
                b[0] = *(const unsigned*)bb;
                b[1] = *(const unsigned*)(bb + 16);
                MMA(c0, a, b);
                bb += 8 * 560;
                b[0] = *(const unsigned*)bb;
                b[1] = *(const unsigned*)(bb + 16);
                MMA(c1, a, b);
            }
            float* d = out + (size_t)(nodeBase + mr + r0) * 144 + c2;
            *(float2*)d = make_float2(c0[0], c0[1]);
            *(float2*)(d + 8 * 144) = make_float2(c0[2], c0[3]);
            *(float2*)(d + 8) = make_float2(c1[0], c1[1]);
            *(float2*)(d + 8 * 144 + 8) = make_float2(c1[2], c1[3]);
            // out2 k=4, nh=1
            float c[4] = {0.f, 0.f, 0.f, 0.f};
            for (int ks = 0; ks < 9; ++ks) {
                LDSM4(a, lbase + 1696 + ks * 32);
                const char* bb = sm + SB2B + (size_t)(8 + r0) * 304 + ks * 32 + c2 * 2;
                b[0] = *(const unsigned*)bb;
                b[1] = *(const unsigned*)(bb + 16);
                MMA(c, a, b);
            }
            float* dd = out + (size_t)(nodeBase + mr + r0) * 144 + 64 + 5 * (8 + c2) + 4;
            dd[0] = c[0]; dd[5] = c[1];
            float* d2 = dd + (size_t)8 * 144;
            d2[0] = c[2]; d2[5] = c[3];
        } else {
            // out2 k = {0,1} (sel 2) or {2,3} (sel 3), both n-halves each
            const int kb = (sel - 2) * 2;
            for (int kk = 0; kk < 2; ++kk) {
                const int k5 = kb + kk;
                const int akc = (272 + 144 * k5) * 2;
                float c0[4] = {0.f, 0.f, 0.f, 0.f}, c1[4] = {0.f, 0.f, 0.f, 0.f};
                for (int ks = 0; ks < 9; ++ks) {
                    LDSM4(a, lbase + akc + ks * 32);
                    const char* bb = sm + SB2A + (size_t)r0 * 304 + ks * 32 + c2 * 2;
                    b[0] = *(const unsigned*)bb;
                    b[1] = *(const unsigned*)(bb + 16);
                    MMA(c0, a, b);
                    bb += 8 * 304;
                    b[0] = *(const unsigned*)bb;
                    b[1] = *(const unsigned*)(bb + 16);
                    MMA(c1, a, b);
                }
                float* d = out + (size_t)(nodeBase + mr + r0) * 144 + 64 + 5 * c2 + k5;
                d[0] = c0[0]; d[5] = c0[1];
                float* d2 = d + (size_t)8 * 144;
                d2[0] = c0[2]; d2[5] = c0[3];
                float* e = d + 40;
                e[0] = c1[0]; e[5] = c1[1];
                float* e2 = e + (size_t)8 * 144;
                e2[0] = c1[2]; e2[5] = c1[3];
            }
        }
    }
    __syncthreads();

    // ---- out1 scalar: 8 threads/node, thread q -> w = 2q..2q+1 ----
    {
        const int node = t >> 3, q = t & 7;
        const float4* xr = (const float4*)(sm + SX) + node * 16;
        const half* gr = (const half*)(sm + SG + (size_t)node * 528);
        float acc[6];
#pragma unroll
        for (int j = 0; j < 6; ++j) acc[j] = 0.f;
#pragma unroll 4
        for (int u = 0; u < 16; ++u) {
            float4 xv = xr[u];
            half2 g01 = *(const half2*)(gr + u * 16 + q * 2);
            float2 f01 = __half22float2(g01);
            acc[0] = fmaf(xv.y, f01.x, acc[0]);
            acc[1] = fmaf(xv.z, f01.x, acc[1]);
            acc[2] = fmaf(xv.w, f01.x, acc[2]);
            acc[3] = fmaf(xv.y, f01.y, acc[3]);
            acc[4] = fmaf(xv.z, f01.y, acc[4]);
            acc[5] = fmaf(xv.w, f01.y, acc[5]);
        }
        float* d = out + (size_t)(nodeBase + node) * 144 + 16 + 6 * q;
        *(float2*)(d + 0) = make_float2(acc[0], acc[1]);
        *(float2*)(d + 2) = make_float2(acc[2], acc[3]);
        *(float2*)(d + 4) = make_float2(acc[4], acc[5]);
    }
}

extern "C" void kernel_launch(void* const* d_in, const int* in_sizes, int n_in,
                              void* d_out, int out_size) {
    const float* nf   = (const float*)d_in[0];
    const float* nm   = (const float*)d_in[1];
    const float* w000 = (const float*)d_in[2];
    const float* w101 = (const float*)d_in[3];
    const float* w110 = (const float*)d_in[4];
    const float* w112 = (const float*)d_in[5];
    const int nnodes = in_sizes[0] / 64;

    prep_kernel<<<32, 256>>>(w000, w101, w110, w112);

    cudaFuncSetAttribute(tsq_kernel, cudaFuncAttributeMaxDynamicSharedMemorySize, SMEM_BYTES);
    const int grid = (nnodes + NODES - 1) / NODES;
    tsq_kernel<<<grid, NT, SMEM_BYTES>>>(nf, nm, (float*)d_out, nnodes);
}

// round 14
// speedup vs baseline: 1.1561x; 1.1561x over previous
#include <cuda_runtime.h>
#include <cuda_fp16.h>
#include <cstdint>

#define NT 256
#define NODES 64
#define AR 2064
// smem byte offsets
#define SX    0
#define SA    16384
#define SB0   148480
#define SB2A  157440
#define SB2B  162304
#define SB1   167168
#define SLUT  179456
#define SG    180000
#define SMEM_BYTES 213792
#define WT_BYTES 31520

__device__ __align__(16) char g_Wt[WT_BYTES];

__device__ __forceinline__ void decode_pair(int p, int& u, int& v) {
    int uu = 0, r = p;
    while (r >= 16 - uu) { r -= 16 - uu; ++uu; }
    u = uu; v = uu + r;
}

// padded-row weight layout: B0 rows 280 halves (560B), B2 rows 152 halves (304B), B1 rows 24 halves (48B)
__global__ void prep_kernel(const float* __restrict__ w000, const float* __restrict__ w101,
                            const float* __restrict__ w110, const float* __restrict__ w112) {
    const float A000  = 0.044194173824159216f;
    const float A110  = 0.025515518153991442f;
    const float A101  = 0.0625f;
    const int tid = blockIdx.x * blockDim.x + threadIdx.x;
    const int nth = gridDim.x * blockDim.x;
    half* B0  = (half*)g_Wt;                 // 16 x 280
    half* B2A = (half*)(g_Wt + 8960);        // 16 x 152
    half* B2B = (half*)(g_Wt + 13824);       // 16 x 152
    half* B1  = (half*)(g_Wt + 18688);       // 256 x 24
    unsigned* LUT = (unsigned*)(g_Wt + 30976);  // 68 duo entries

    for (int idx = tid; idx < 16 * 272; idx += nth) {
        int w = idx / 272, c = idx % 272;
        int p = (c < 136) ? c : c - 136;
        int u, v; decode_pair(p, u, v);
        const float* src = (c < 136) ? w000 : w110;
        float sc = (c < 136) ? A000 : A110;
        float cc = src[u * 256 + v * 16 + w];
        if (u != v) cc += src[v * 256 + u * 16 + w];
        B0[w * 280 + c] = __float2half_rn(cc * sc);
    }
    for (int idx = tid; idx < 16 * 144; idx += nth) {
        int w = idx / 144, p = idx % 144;
        float cc = 0.f;
        if (p < 136) {
            int u, v; decode_pair(p, u, v);
            cc = w112[u * 256 + v * 16 + w];
            if (u != v) cc += w112[v * 256 + u * 16 + w];
        }
        B2A[w * 152 + p] = __float2half_rn(cc * A000);  // A112/sqrt(10) == A000
        B2B[w * 152 + p] = __float2half_rn(cc * A110);  // A112/sqrt(30) == A110
    }
    for (int idx = tid; idx < 256 * 24; idx += nth) {
        int n = idx / 24, kk = idx % 24;
        int u = n >> 4, w = n & 15;
        float val = (kk < 16) ? w101[u * 256 + kk * 16 + w] * A101 : 0.f;
        B1[idx] = __float2half_rn(val);
    }
    for (int d = tid; d < 68; d += nth) {
        int u0, v0, u1, v1;
        decode_pair(2 * d, u0, v0);
        decode_pair(2 * d + 1, u1, v1);
        LUT[d] = (unsigned)u0 | ((unsigned)v0 << 8) | ((unsigned)u1 << 16) | ((unsigned)v1 << 24);
    }
}

#define MMA(c, a, b) asm volatile( \
    "mma.sync.aligned.m16n8k16.row.col.f32.f16.f16.f32 " \
    "{%0,%1,%2,%3}, {%4,%5,%6,%7}, {%8,%9}, {%0,%1,%2,%3};" \
    : "+f"(c[0]), "+f"(c[1]), "+f"(c[2]), "+f"(c[3]) \
    : "r"(a[0]), "r"(a[1]), "r"(a[2]), "r"(a[3]), "r"(b[0]), "r"(b[1]))

__global__ void __launch_bounds__(NT)
tsq_kernel(const float* __restrict__ nf, const float* __restrict__ nm,
           float* __restrict__ out, int nnodes) {
    extern __shared__ char sm[];
    const int t = threadIdx.x;
    const int nodeBase = blockIdx.x * NODES;

    // stage weights/LUT (g_Wt -> SB0.. contiguous)
    {
        const uint4* src = (const uint4*)g_Wt;
        uint4* dst = (uint4*)(sm + SB0);
        for (int i = t; i < WT_BYTES / 16; i += NT) dst[i] = src[i];
    }
    // stage x = nf+nm into float4 sX[node][u] = {x0[u], x1[u][0..2]}
    {
        const float4* a4 = (const float4*)nf;
        const float4* b4 = (const float4*)nm;
        float* sx = (float*)(sm + SX);
        const int limit = nnodes * 16;
        for (int i = t; i < NODES * 16; i += NT) {
            int gi = nodeBase * 16 + i;
            float4 a = make_float4(0.f, 0.f, 0.f, 0.f), b = a;
            if (gi < limit) { a = a4[gi]; b = b4[gi]; }
            int node = i >> 4, c0 = (i & 15) << 2;
            float vals[4] = {a.x + b.x, a.y + b.y, a.z + b.z, a.w + b.w};
#pragma unroll
            for (int j = 0; j < 4; ++j) {
                int c = c0 + j, u, f;
                if (c < 16) { u = c; f = 0; }
                else { u = (c - 16) / 3; f = 1 + (c - 16) % 3; }
                sx[(node * 16 + u) * 4 + f] = vals[j];
            }
        }
    }
    __syncthreads();

    // ---- basis: 4 threads/node, duo = pairs (2d, 2d+1), half2 stores ----
    {
        const int node = t >> 2, q = t & 3;
        const float4* xr = (const float4*)(sm + SX) + node * 16;
        half* arow = (half*)(sm + SA + (size_t)node * AR);
        const unsigned* lut = (const unsigned*)(sm + SLUT);
        // zero the 5 K-pad gaps (cols 408+144g .. +7)
        for (int g = q; g < 5; g += 4) {
            uint4 z = make_uint4(0, 0, 0, 0);
            *(uint4*)(arow + 408 + 144 * g) = z;
        }
        for (int d = q; d < 68; d += 4) {
            unsigned uv = lut[d];
            float4 a0 = xr[uv & 255], b0 = xr[(uv >> 8) & 255];
            float4 a1 = xr[(uv >> 16) & 255], b1 = xr[uv >> 24];
            // pair 0
            float y0   = a0.x * b0.x;
            float p00 = a0.y * b0.y, p01 = a0.y * b0.z, p02 = a0.y * b0.w;
            float p10 = a0.z * b0.y, p11 = a0.z * b0.z, p12 = a0.z * b0.w;
            float p20 = a0.w * b0.y, p21 = a0.w * b0.z, p22 = a0.w * b0.w;
            float h0 = p00 + p11;
            // pair 1
            float y1   = a1.x * b1.x;
            float q00 = a1.y * b1.y, q01 = a1.y * b1.z, q02 = a1.y * b1.w;
            float q10 = a1.z * b1.y, q11 = a1.z * b1.z, q12 = a1.z * b1.w;
            float q20 = a1.w * b1.y, q21 = a1.w * b1.z, q22 = a1.w * b1.w;
            float h1 = q00 + q11;
            const int c = 2 * d;
            *(half2*)(arow + c)       = __floats2half2_rn(y0, y1);
            *(half2*)(arow + 136 + c) = __floats2half2_rn(h0 + p22, h1 + q22);
            *(half2*)(arow + 272 + c) = __floats2half2_rn(p01 + p10, q01 + q10);
            *(half2*)(arow + 416 + c) = __floats2half2_rn(p02 + p20, q02 + q20);
            *(half2*)(arow + 560 + c) = __floats2half2_rn(p12 + p21, q12 + q21);
            *(half2*)(arow + 704 + c) = __floats2half2_rn(p00 - p11, q00 - q11);
            *(half2*)(arow + 848 + c) = __floats2half2_rn(fmaf(2.f, p22, -h0), fmaf(2.f, q22, -h1));
        }
        // x0 row: cols 992..1007; thread q stores half2 at 992+2q and 992+8+2q
        *(half2*)(arow + 992 + 2 * q) = __floats2half2_rn(xr[2 * q].x, xr[2 * q + 1].x);
        *(half2*)(arow + 1000 + 2 * q) = __floats2half2_rn(xr[8 + 2 * q].x, xr[9 + 2 * q].x);
    }
    __syncthreads();

    // ---- MMA phase: 8 warps = mr(4) x nh(2); dual-accumulator chains ----
    {
        const int w = t >> 5, lane = t & 31;
        const int mr = (w & 3) * 16, nh = w >> 2;
        const int r0 = lane >> 2, c2 = (lane & 3) * 2;
        const char* Abase = sm + SA + (size_t)(mr + r0) * AR + c2 * 2;
        unsigned a[4], b[2];

        // G = x0 * B1^T : K=16, warp's 16 n-tiles (independent chains)
        {
            a[0] = *(const unsigned*)(Abase + 992 * 2);
            a[1] = *(const unsigned*)(Abase + 992 * 2 + 8 * AR);
            a[2] = *(const unsigned*)(Abase + 992 * 2 + 16);
            a[3] = *(const unsigned*)(Abase + 992 * 2 + 8 * AR + 16);
            for (int j = 0; j < 16; ++j) {
                int nt = nh * 16 + j;
                const char* bb = sm + SB1 + (size_t)(nt * 8 + r0) * 48 + c2 * 2;
                b[0] = *(const unsigned*)bb;
                b[1] = *(const unsigned*)(bb + 16);
                float c[4] = {0.f, 0.f, 0.f, 0.f};
                MMA(c, a, b);
                int ncol = nt * 8 + c2;
                *(half2*)(sm + SG + (size_t)(mr + r0) * 528 + ncol * 2) =
                    __floats2half2_rn(c[0], c[1]);
                *(half2*)(sm + SG + (size_t)(mr + r0 + 8) * 528 + ncol * 2) =
                    __floats2half2_rn(c[2], c[3]);
            }
        }
        // out0 = [y|s] * B0^T : K=272, dual accumulators (chain 17 -> 9)
        {
            float cc[2][4] = {{0.f, 0.f, 0.f, 0.f}, {0.f, 0.f, 0.f, 0.f}};
#pragma unroll
            for (int ks = 0; ks < 17; ++ks) {
                const char* ab = Abase + ks * 32;
                a[0] = *(const unsigned*)ab;
                a[1] = *(const unsigned*)(ab + 8 * AR);
                a[2] = *(const unsigned*)(ab + 16);
                a[3] = *(const unsigned*)(ab + 8 * AR + 16);
                const char* bb = sm + SB0 + (size_t)(nh * 8 + r0) * 560 + ks * 32 + c2 * 2;
                b[0] = *(const unsigned*)bb;
                b[1] = *(const unsigned*)(bb + 16);
                MMA(cc[ks & 1], a, b);
            }
            float* d = out + (size_t)(nodeBase + mr + r0) * 144 + nh * 8 + c2;
            *(float2*)d = make_float2(cc[0][0] + cc[1][0], cc[0][1] + cc[1][1]);
            *(float2*)(d + 8 * 144) = make_float2(cc[0][2] + cc[1][2], cc[0][3] + cc[1][3]);
        }
        // out2_k = t_k * B2^T : K=144, k=0..4, dual accumulators (chain 9 -> 5)
        for (int k5 = 0; k5 < 5; ++k5) {
            float cc[2][4] = {{0.f, 0.f, 0.f, 0.f}, {0.f, 0.f, 0.f, 0.f}};
            const int sb = (k5 < 4) ? SB2A : SB2B;
            const int akc = (272 + 144 * k5) * 2;
#pragma unroll
            for (int ks = 0; ks < 9; ++ks) {
                const char* ab = Abase + akc + ks * 32;
                a[0] = *(const unsigned*)ab;
                a[1] = *(const unsigned*)(ab + 8 * AR);
                a[2] = *(const unsigned*)(ab + 16);
                a[3] = *(const unsigned*)(ab + 8 * AR + 16);
                const char* bb = sm + sb + (size_t)(nh * 8 + r0) * 304 + ks * 32 + c2 * 2;
                b[0] = *(const unsigned*)bb;
                b[1] = *(const unsigned*)(bb + 16);
                MMA(cc[ks & 1], a, b);
            }
            int wc = nh * 8 + c2;
            float* d = out + (size_t)(nodeBase + mr + r0) * 144 + 64 + 5 * wc + k5;
            d[0] = cc[0][0] + cc[1][0]; d[5] = cc[0][1] + cc[1][1];
            float* d2 = d + (size_t)8 * 144;
            d2[0] = cc[0][2] + cc[1][2]; d2[5] = cc[0][3] + cc[1][3];
        }
    }
    __syncthreads();

    // ---- out1 scalar: 4 threads/node, thread q -> w = 4q..4q+3 ----
    {
        const int node = t >> 2, q = t & 3;
        const float4* xr = (const float4*)(sm + SX) + node * 16;
        const half* gr = (const half*)(sm + SG + (size_t)node * 528);
        float acc[12];
#pragma unroll
        for (int j = 0; j < 12; ++j) acc[j] = 0.f;
#pragma unroll 4
        for (int u = 0; u < 16; ++u) {
            float4 xv = xr[u];
            half2 g01 = *(const half2*)(gr + u * 16 + q * 4);
            half2 g23 = *(const half2*)(gr + u * 16 + q * 4 + 2);
            float2 f01 = __half22float2(g01), f23 = __half22float2(g23);
            float gv[4] = {f01.x, f01.y, f23.x, f23.y};
#pragma unroll
            for (int j = 0; j < 4; ++j) {
                acc[j * 3 + 0] = fmaf(xv.y, gv[j], acc[j * 3 + 0]);
                acc[j * 3 + 1] = fmaf(xv.z, gv[j], acc[j * 3 + 1]);
                acc[j * 3 + 2] = fmaf(xv.w, gv[j], acc[j * 3 + 2]);
            }
        }
        float* d = out + (size_t)(nodeBase + node) * 144 + 16 + 12 * q;
        *(float4*)(d + 0) = make_float4(acc[0], acc[1], acc[2],  acc[3]);
        *(float4*)(d + 4) = make_float4(acc[4], acc[5], acc[6],  acc[7]);
        *(float4*)(d + 8) = make_float4(acc[8], acc[9], acc[10], acc[11]);
    }
}

extern "C" void kernel_launch(void* const* d_in, const int* in_sizes, int n_in,
                              void* d_out, int out_size) {
    const float* nf   = (const float*)d_in[0];
    const float* nm   = (const float*)d_in[1];
    const float* w000 = (const float*)d_in[2];
    const float* w101 = (const float*)d_in[3];
    const float* w110 = (const float*)d_in[4];
    const float* w112 = (const float*)d_in[5];
    const int nnodes = in_sizes[0] / 64;

    prep_kernel<<<32, 256>>>(w000, w101, w110, w112);

    cudaFuncSetAttribute(tsq_kernel, cudaFuncAttributeMaxDynamicSharedMemorySize, SMEM_BYTES);
    const int grid = (nnodes + NODES - 1) / NODES;
    tsq_kernel<<<grid, NT, SMEM_BYTES>>>(nf, nm, (float*)d_out, nnodes);
}

// round 16
// speedup vs baseline: 1.6505x; 1.4277x over previous
#include <cuda_runtime.h>
#include <cuda_fp16.h>
#include <cstdint>

#define NT 256
#define NODES 32
#define AR 2032
// smem byte offsets
#define SX    0
#define SA    8192
#define SB0   73216
#define SB2A  82176
#define SB1   87040
#define SLUT  95232
#define SG    95504
#define SMEM_BYTES 112400
#define WT_BYTES 22288

__device__ __align__(16) char g_Wt[WT_BYTES];

__device__ __forceinline__ void decode_pair(int p, int& u, int& v) {
    int uu = 0, r = p;
    while (r >= 16 - uu) { r -= 16 - uu; ++uu; }
    u = uu; v = uu + r;
}

// weight layout in g_Wt: B0 16x280 (560B rows) @0, B2A 16x152 (304B rows) @8960,
//                        B1 256x16 (32B rows) @13824, LUT 68 duos @22016
__global__ void prep_kernel(const float* __restrict__ w000, const float* __restrict__ w101,
                            const float* __restrict__ w110, const float* __restrict__ w112) {
    const float A000  = 0.044194173824159216f;
    const float A110  = 0.025515518153991442f;
    const float A101  = 0.0625f;
    const int tid = blockIdx.x * blockDim.x + threadIdx.x;
    const int nth = gridDim.x * blockDim.x;
    half* B0  = (half*)g_Wt;
    half* B2A = (half*)(g_Wt + 8960);
    half* B1  = (half*)(g_Wt + 13824);
    unsigned* LUT = (unsigned*)(g_Wt + 22016);

    for (int idx = tid; idx < 16 * 272; idx += nth) {
        int w = idx / 272, c = idx % 272;
        int p = (c < 136) ? c : c - 136;
        int u, v; decode_pair(p, u, v);
        const float* src = (c < 136) ? w000 : w110;
        float sc = (c < 136) ? A000 : A110;
        float cc = src[u * 256 + v * 16 + w];
        if (u != v) cc += src[v * 256 + u * 16 + w];
        B0[w * 280 + c] = __float2half_rn(cc * sc);
    }
    for (int idx = tid; idx < 16 * 144; idx += nth) {
        int w = idx / 144, p = idx % 144;
        float cc = 0.f;
        if (p < 136) {
            int u, v; decode_pair(p, u, v);
            cc = w112[u * 256 + v * 16 + w];
            if (u != v) cc += w112[v * 256 + u * 16 + w];
        }
        B2A[w * 152 + p] = __float2half_rn(cc * A000);  // A112/sqrt(10) == A000
    }
    for (int idx = tid; idx < 256 * 16; idx += nth) {
        int n = idx >> 4, kk = idx & 15;
        int u = n >> 4, w = n & 15;
        B1[idx] = __float2half_rn(w101[u * 256 + kk * 16 + w] * A101);
    }
    for (int d = tid; d < 68; d += nth) {
        int u0, v0, u1, v1;
        decode_pair(2 * d, u0, v0);
        decode_pair(2 * d + 1, u1, v1);
        LUT[d] = (unsigned)u0 | ((unsigned)v0 << 8) | ((unsigned)u1 << 16) | ((unsigned)v1 << 24);
    }
}

#define MMA(c, a, b) asm volatile( \
    "mma.sync.aligned.m16n8k16.row.col.f32.f16.f16.f32 " \
    "{%0,%1,%2,%3}, {%4,%5,%6,%7}, {%8,%9}, {%0,%1,%2,%3};" \
    : "+f"(c[0]), "+f"(c[1]), "+f"(c[2]), "+f"(c[3]) \
    : "r"(a[0]), "r"(a[1]), "r"(a[2]), "r"(a[3]), "r"(b[0]), "r"(b[1]))

__global__ void __launch_bounds__(NT)
tsq_kernel(const float* __restrict__ nf, const float* __restrict__ nm,
           float* __restrict__ out, int nnodes) {
    extern __shared__ char sm[];
    const int t = threadIdx.x;
    const int nodeBase = blockIdx.x * NODES;

    // stage weights/LUT (g_Wt -> SB0.. contiguous)
    {
        const uint4* src = (const uint4*)g_Wt;
        uint4* dst = (uint4*)(sm + SB0);
        for (int i = t; i < WT_BYTES / 16; i += NT) dst[i] = src[i];
    }
    // stage x = nf+nm into float4 sX[node][u] = {x0[u], x1[u][0..2]}
    {
        const float4* a4 = (const float4*)nf;
        const float4* b4 = (const float4*)nm;
        float* sx = (float*)(sm + SX);
        const int limit = nnodes * 16;
        for (int i = t; i < NODES * 16; i += NT) {
            int gi = nodeBase * 16 + i;
            float4 a = make_float4(0.f, 0.f, 0.f, 0.f), b = a;
            if (gi < limit) { a = a4[gi]; b = b4[gi]; }
            int node = i >> 4, c0 = (i & 15) << 2;
            float vals[4] = {a.x + b.x, a.y + b.y, a.z + b.z, a.w + b.w};
#pragma unroll
            for (int j = 0; j < 4; ++j) {
                int c = c0 + j, u, f;
                if (c < 16) { u = c; f = 0; }
                else { u = (c - 16) / 3; f = 1 + (c - 16) % 3; }
                sx[(node * 16 + u) * 4 + f] = vals[j];
            }
        }
    }
    __syncthreads();

    // ---- basis: 8 threads/node, duos (2d,2d+1), half2 stores; t4 pre-scaled by 1/sqrt3 ----
    {
        const float RT3I = 0.5773502691896258f;  // A110/A000
        const int node = t >> 3, q = t & 7;
        const float4* xr = (const float4*)(sm + SX) + node * 16;
        half* arow = (half*)(sm + SA + (size_t)node * AR);
        const unsigned* lut = (const unsigned*)(sm + SLUT);
        if (q < 5) {
            uint4 z = make_uint4(0, 0, 0, 0);
            *(uint4*)(arow + 408 + 144 * q) = z;   // K-pad gaps
        }
        for (int d = q; d < 68; d += 8) {
            unsigned uv = lut[d];
            float4 a0 = xr[uv & 255], b0 = xr[(uv >> 8) & 255];
            float4 a1 = xr[(uv >> 16) & 255], b1 = xr[uv >> 24];
            float y0  = a0.x * b0.x;
            float p00 = a0.y * b0.y, p01 = a0.y * b0.z, p02 = a0.y * b0.w;
            float p10 = a0.z * b0.y, p11 = a0.z * b0.z, p12 = a0.z * b0.w;
            float p20 = a0.w * b0.y, p21 = a0.w * b0.z, p22 = a0.w * b0.w;
            float h0 = p00 + p11;
            float y1  = a1.x * b1.x;
            float q00 = a1.y * b1.y, q01 = a1.y * b1.z, q02 = a1.y * b1.w;
            float q10 = a1.z * b1.y, q11 = a1.z * b1.z, q12 = a1.z * b1.w;
            float q20 = a1.w * b1.y, q21 = a1.w * b1.z, q22 = a1.w * b1.w;
            float h1 = q00 + q11;
            const int c = 2 * d;
            *(half2*)(arow + c)       = __floats2half2_rn(y0, y1);
            *(half2*)(arow + 136 + c) = __floats2half2_rn(h0 + p22, h1 + q22);
            *(half2*)(arow + 272 + c) = __floats2half2_rn(p01 + p10, q01 + q10);
            *(half2*)(arow + 416 + c) = __floats2half2_rn(p02 + p20, q02 + q20);
            *(half2*)(arow + 560 + c) = __floats2half2_rn(p12 + p21, q12 + q21);
            *(half2*)(arow + 704 + c) = __floats2half2_rn(p00 - p11, q00 - q11);
            *(half2*)(arow + 848 + c) = __floats2half2_rn(fmaf(2.f, p22, -h0) * RT3I,
                                                          fmaf(2.f, q22, -h1) * RT3I);
        }
        *(half2*)(arow + 992 + 2 * q) = __floats2half2_rn(xr[2 * q].x, xr[2 * q + 1].x);
    }
    __syncthreads();

    // ---- MMA phase: 8 warps = mt(2) x nh(2) x sel(2) ----
    {
        const int w = t >> 5, lane = t & 31;
        const int mt = w & 1, nh = (w >> 1) & 1, sel = w >> 2;
        const int mr = mt * 16;
        const int r0 = lane >> 2, c2 = (lane & 3) * 2;
        const char* Abase = sm + SA + (size_t)(mr + r0) * AR + c2 * 2;
        unsigned a[4], b[2];
        int klo, khi;

        if (sel == 0) {
            // G = x0 * B1^T : K=16, this nh's 16 n-tiles
            a[0] = *(const unsigned*)(Abase + 1984);
            a[1] = *(const unsigned*)(Abase + 1984 + 8 * AR);
            a[2] = *(const unsigned*)(Abase + 1984 + 16);
            a[3] = *(const unsigned*)(Abase + 1984 + 8 * AR + 16);
            for (int j = 0; j < 16; ++j) {
                int nt = nh * 16 + j;
                const char* bb = sm + SB1 + (size_t)(nt * 8 + r0) * 32 + c2 * 2;
                b[0] = *(const unsigned*)bb;
                b[1] = *(const unsigned*)(bb + 16);
                float c[4] = {0.f, 0.f, 0.f, 0.f};
                MMA(c, a, b);
                int ncol = nt * 8 + c2;
                *(half2*)(sm + SG + (size_t)(mr + r0) * 528 + ncol * 2) =
                    __floats2half2_rn(c[0], c[1]);
                *(half2*)(sm + SG + (size_t)(mr + r0 + 8) * 528 + ncol * 2) =
                    __floats2half2_rn(c[2], c[3]);
            }
            klo = 0; khi = 1;
        } else {
            // out0 = [y|s] * B0^T : K=272, dual accumulators
            float cc[2][4] = {{0.f, 0.f, 0.f, 0.f}, {0.f, 0.f, 0.f, 0.f}};
#pragma unroll
            for (int ks = 0; ks < 17; ++ks) {
                const char* ab = Abase + ks * 32;
                a[0] = *(const unsigned*)ab;
                a[1] = *(const unsigned*)(ab + 8 * AR);
                a[2] = *(const unsigned*)(ab + 16);
                a[3] = *(const unsigned*)(ab + 8 * AR + 16);
                const char* bb = sm + SB0 + (size_t)(nh * 8 + r0) * 560 + ks * 32 + c2 * 2;
                b[0] = *(const unsigned*)bb;
                b[1] = *(const unsigned*)(bb + 16);
                MMA(cc[ks & 1], a, b);
            }
            float* d = out + (size_t)(nodeBase + mr + r0) * 144 + nh * 8 + c2;
            *(float2*)d = make_float2(cc[0][0] + cc[1][0], cc[0][1] + cc[1][1]);
            *(float2*)(d + 8 * 144) = make_float2(cc[0][2] + cc[1][2], cc[0][3] + cc[1][3]);
            klo = 2; khi = 4;
        }

        // out2_k = t_k * B2A^T : K=144 (t4 pre-scaled), dual accumulators
        for (int k5 = klo; k5 <= khi; ++k5) {
            float cc[2][4] = {{0.f, 0.f, 0.f, 0.f}, {0.f, 0.f, 0.f, 0.f}};
            const int akc = (272 + 144 * k5) * 2;
#pragma unroll
            for (int ks = 0; ks < 9; ++ks) {
                const char* ab = Abase + akc + ks * 32;
                a[0] = *(const unsigned*)ab;
                a[1] = *(const unsigned*)(ab + 8 * AR);
                a[2] = *(const unsigned*)(ab + 16);
                a[3] = *(const unsigned*)(ab + 8 * AR + 16);
                const char* bb = sm + SB2A + (size_t)(nh * 8 + r0) * 304 + ks * 32 + c2 * 2;
                b[0] = *(const unsigned*)bb;
                b[1] = *(const unsigned*)(bb + 16);
                MMA(cc[ks & 1], a, b);
            }
            int wc = nh * 8 + c2;
            float* d = out + (size_t)(nodeBase + mr + r0) * 144 + 64 + 5 * wc + k5;
            d[0] = cc[0][0] + cc[1][0]; d[5] = cc[0][1] + cc[1][1];
            float* d2 = d + (size_t)8 * 144;
            d2[0] = cc[0][2] + cc[1][2]; d2[5] = cc[0][3] + cc[1][3];
        }
    }
    __syncthreads();

    // ---- out1 scalar: 8 threads/node, thread q -> w = 2q..2q+1 ----
    {
        const int node = t >> 3, q = t & 7;
        const float4* xr = (const float4*)(sm + SX) + node * 16;
        const half* gr = (const half*)(sm + SG + (size_t)node * 528);
        float acc[6];
#pragma unroll
        for (int j = 0; j < 6; ++j) acc[j] = 0.f;
#pragma unroll 4
        for (int u = 0; u < 16; ++u) {
            float4 xv = xr[u];
            half2 g01 = *(const half2*)(gr + u * 16 + q * 2);
            float2 f01 = __half22float2(g01);
            acc[0] = fmaf(xv.y, f01.x, acc[0]);
            acc[1] = fmaf(xv.z, f01.x, acc[1]);
            acc[2] = fmaf(xv.w, f01.x, acc[2]);
            acc[3] = fmaf(xv.y, f01.y, acc[3]);
            acc[4] = fmaf(xv.z, f01.y, acc[4]);
            acc[5] = fmaf(xv.w, f01.y, acc[5]);
        }
        float* d = out + (size_t)(nodeBase + node) * 144 + 16 + 6 * q;
        *(float2*)(d + 0) = make_float2(acc[0], acc[1]);
        *(float2*)(d + 2) = make_float2(acc[2], acc[3]);
        *(float2*)(d + 4) = make_float2(acc[4], acc[5]);
    }
}

extern "C" void kernel_launch(void* const* d_in, const int* in_sizes, int n_in,
                              void* d_out, int out_size) {
    const float* nf   = (const float*)d_in[0];
    const float* nm   = (const float*)d_in[1];
    const float* w000 = (const float*)d_in[2];
    const float* w101 = (const float*)d_in[3];
    const float* w110 = (const float*)d_in[4];
    const float* w112 = (const float*)d_in[5];
    const int nnodes = in_sizes[0] / 64;

    prep_kernel<<<32, 256>>>(w000, w101, w110, w112);

    cudaFuncSetAttribute(tsq_kernel, cudaFuncAttributeMaxDynamicSharedMemorySize, SMEM_BYTES);
    const int grid = (nnodes + NODES - 1) / NODES;
    tsq_kernel<<<grid, NT, SMEM_BYTES>>>(nf, nm, (float*)d_out, nnodes);
}

// round 17
// speedup vs baseline: 1.7302x; 1.0483x over previous
#include <cuda_runtime.h>
#include <cuda_fp16.h>
#include <cstdint>

#define NT 256
#define NODES 32
#define AR 2032
#define SOR 148   // staged-output row stride in floats
// smem byte offsets
#define SX    0
#define SA    8192
#define SB0   73216
#define SB2A  82176
#define SB1   87040
#define SLUT  95232
#define SG    95504
#define SMEM_BYTES 112400
#define WT_BYTES 22288

__device__ __align__(16) char g_Wt[WT_BYTES];

__device__ __forceinline__ void decode_pair(int p, int& u, int& v) {
    int uu = 0, r = p;
    while (r >= 16 - uu) { r -= 16 - uu; ++uu; }
    u = uu; v = uu + r;
}

// weight layout in g_Wt: B0 16x280 (560B rows) @0, B2A 16x152 (304B rows) @8960,
//                        B1 256x16 (32B rows) @13824, LUT 68 duos @22016
__global__ void prep_kernel(const float* __restrict__ w000, const float* __restrict__ w101,
                            const float* __restrict__ w110, const float* __restrict__ w112) {
    const float A000  = 0.044194173824159216f;
    const float A110  = 0.025515518153991442f;
    const float A101  = 0.0625f;
    const int tid = blockIdx.x * blockDim.x + threadIdx.x;
    const int nth = gridDim.x * blockDim.x;
    half* B0  = (half*)g_Wt;
    half* B2A = (half*)(g_Wt + 8960);
    half* B1  = (half*)(g_Wt + 13824);
    unsigned* LUT = (unsigned*)(g_Wt + 22016);

    for (int idx = tid; idx < 16 * 272; idx += nth) {
        int w = idx / 272, c = idx % 272;
        int p = (c < 136) ? c : c - 136;
        int u, v; decode_pair(p, u, v);
        const float* src = (c < 136) ? w000 : w110;
        float sc = (c < 136) ? A000 : A110;
        float cc = src[u * 256 + v * 16 + w];
        if (u != v) cc += src[v * 256 + u * 16 + w];
        B0[w * 280 + c] = __float2half_rn(cc * sc);
    }
    for (int idx = tid; idx < 16 * 144; idx += nth) {
        int w = idx / 144, p = idx % 144;
        float cc = 0.f;
        if (p < 136) {
            int u, v; decode_pair(p, u, v);
            cc = w112[u * 256 + v * 16 + w];
            if (u != v) cc += w112[v * 256 + u * 16 + w];
        }
        B2A[w * 152 + p] = __float2half_rn(cc * A000);  // A112/sqrt(10) == A000
    }
    for (int idx = tid; idx < 256 * 16; idx += nth) {
        int n = idx >> 4, kk = idx & 15;
        int u = n >> 4, w = n & 15;
        B1[idx] = __float2half_rn(w101[u * 256 + kk * 16 + w] * A101);
    }
    for (int d = tid; d < 68; d += nth) {
        int u0, v0, u1, v1;
        decode_pair(2 * d, u0, v0);
        decode_pair(2 * d + 1, u1, v1);
        LUT[d] = (unsigned)u0 | ((unsigned)v0 << 8) | ((unsigned)u1 << 16) | ((unsigned)v1 << 24);
    }
}

#define MMA(c, a, b) asm volatile( \
    "mma.sync.aligned.m16n8k16.row.col.f32.f16.f16.f32 " \
    "{%0,%1,%2,%3}, {%4,%5,%6,%7}, {%8,%9}, {%0,%1,%2,%3};" \
    : "+f"(c[0]), "+f"(c[1]), "+f"(c[2]), "+f"(c[3]) \
    : "r"(a[0]), "r"(a[1]), "r"(a[2]), "r"(a[3]), "r"(b[0]), "r"(b[1]))

__global__ void __launch_bounds__(NT)
tsq_kernel(const float* __restrict__ nf, const float* __restrict__ nm,
           float* __restrict__ out, int nnodes) {
    extern __shared__ char sm[];
    const int t = threadIdx.x;
    const int nodeBase = blockIdx.x * NODES;

    // stage weights/LUT (g_Wt -> SB0.. contiguous)
    {
        const uint4* src = (const uint4*)g_Wt;
        uint4* dst = (uint4*)(sm + SB0);
        for (int i = t; i < WT_BYTES / 16; i += NT) dst[i] = src[i];
    }
    // stage x = nf+nm into float4 sX[node][u] = {x0[u], x1[u][0..2]}
    {
        const float4* a4 = (const float4*)nf;
        const float4* b4 = (const float4*)nm;
        float* sx = (float*)(sm + SX);
        const int limit = nnodes * 16;
        for (int i = t; i < NODES * 16; i += NT) {
            int gi = nodeBase * 16 + i;
            float4 a = make_float4(0.f, 0.f, 0.f, 0.f), b = a;
            if (gi < limit) { a = a4[gi]; b = b4[gi]; }
            int node = i >> 4, c0 = (i & 15) << 2;
            float vals[4] = {a.x + b.x, a.y + b.y, a.z + b.z, a.w + b.w};
#pragma unroll
            for (int j = 0; j < 4; ++j) {
                int c = c0 + j, u, f;
                if (c < 16) { u = c; f = 0; }
                else { u = (c - 16) / 3; f = 1 + (c - 16) % 3; }
                sx[(node * 16 + u) * 4 + f] = vals[j];
            }
        }
    }
    __syncthreads();

    // ---- basis: 8 threads/node, duos (2d,2d+1), half2 stores; t4 pre-scaled by 1/sqrt3 ----
    {
        const float RT3I = 0.5773502691896258f;  // A110/A000
        const int node = t >> 3, q = t & 7;
        const float4* xr = (const float4*)(sm + SX) + node * 16;
        half* arow = (half*)(sm + SA + (size_t)node * AR);
        const unsigned* lut = (const unsigned*)(sm + SLUT);
        if (q < 5) {
            uint4 z = make_uint4(0, 0, 0, 0);
            *(uint4*)(arow + 408 + 144 * q) = z;   // K-pad gaps
        }
        for (int d = q; d < 68; d += 8) {
            unsigned uv = lut[d];
            float4 a0 = xr[uv & 255], b0 = xr[(uv >> 8) & 255];
            float4 a1 = xr[(uv >> 16) & 255], b1 = xr[uv >> 24];
            float y0  = a0.x * b0.x;
            float p00 = a0.y * b0.y, p01 = a0.y * b0.z, p02 = a0.y * b0.w;
            float p10 = a0.z * b0.y, p11 = a0.z * b0.z, p12 = a0.z * b0.w;
            float p20 = a0.w * b0.y, p21 = a0.w * b0.z, p22 = a0.w * b0.w;
            float h0 = p00 + p11;
            float y1  = a1.x * b1.x;
            float q00 = a1.y * b1.y, q01 = a1.y * b1.z, q02 = a1.y * b1.w;
            float q10 = a1.z * b1.y, q11 = a1.z * b1.z, q12 = a1.z * b1.w;
            float q20 = a1.w * b1.y, q21 = a1.w * b1.z, q22 = a1.w * b1.w;
            float h1 = q00 + q11;
            const int c = 2 * d;
            *(half2*)(arow + c)       = __floats2half2_rn(y0, y1);
            *(half2*)(arow + 136 + c) = __floats2half2_rn(h0 + p22, h1 + q22);
            *(half2*)(arow + 272 + c) = __floats2half2_rn(p01 + p10, q01 + q10);
            *(half2*)(arow + 416 + c) = __floats2half2_rn(p02 + p20, q02 + q20);
            *(half2*)(arow + 560 + c) = __floats2half2_rn(p12 + p21, q12 + q21);
            *(half2*)(arow + 704 + c) = __floats2half2_rn(p00 - p11, q00 - q11);
            *(half2*)(arow + 848 + c) = __floats2half2_rn(fmaf(2.f, p22, -h0) * RT3I,
                                                          fmaf(2.f, q22, -h1) * RT3I);
        }
        *(half2*)(arow + 992 + 2 * q) = __floats2half2_rn(xr[2 * q].x, xr[2 * q + 1].x);
    }
    __syncthreads();

    // ---- MMA phase: 8 warps = mt(2) x nh(2) x sel(2); results held in regs ----
    {
        const int w = t >> 5, lane = t & 31;
        const int mt = w & 1, nh = (w >> 1) & 1, sel = w >> 2;
        const int mr = mt * 16;
        const int r0 = lane >> 2, c2 = (lane & 3) * 2;
        const char* Abase = sm + SA + (size_t)(mr + r0) * AR + c2 * 2;
        unsigned a[4], b[2];
        float oo[4];                  // out0 (sel1 only)
        float r2[3][4];               // out2 results
        int klo, nk;

        if (sel == 0) {
            // G = x0 * B1^T : K=16, this nh's 16 n-tiles
            a[0] = *(const unsigned*)(Abase + 1984);
            a[1] = *(const unsigned*)(Abase + 1984 + 8 * AR);
            a[2] = *(const unsigned*)(Abase + 1984 + 16);
            a[3] = *(const unsigned*)(Abase + 1984 + 8 * AR + 16);
            for (int j = 0; j < 16; ++j) {
                int nt = nh * 16 + j;
                const char* bb = sm + SB1 + (size_t)(nt * 8 + r0) * 32 + c2 * 2;
                b[0] = *(const unsigned*)bb;
                b[1] = *(const unsigned*)(bb + 16);
                float c[4] = {0.f, 0.f, 0.f, 0.f};
                MMA(c, a, b);
                int ncol = nt * 8 + c2;
                *(half2*)(sm + SG + (size_t)(mr + r0) * 528 + ncol * 2) =
                    __floats2half2_rn(c[0], c[1]);
                *(half2*)(sm + SG + (size_t)(mr + r0 + 8) * 528 + ncol * 2) =
                    __floats2half2_rn(c[2], c[3]);
            }
            klo = 0; nk = 2;
        } else {
            // out0 = [y|s] * B0^T : K=272, dual accumulators
            float cc[2][4] = {{0.f, 0.f, 0.f, 0.f}, {0.f, 0.f, 0.f, 0.f}};
#pragma unroll
            for (int ks = 0; ks < 17; ++ks) {
                const char* ab = Abase + ks * 32;
                a[0] = *(const unsigned*)ab;
                a[1] = *(const unsigned*)(ab + 8 * AR);
                a[2] = *(const unsigned*)(ab + 16);
                a[3] = *(const unsigned*)(ab + 8 * AR + 16);
                const char* bb = sm + SB0 + (size_t)(nh * 8 + r0) * 560 + ks * 32 + c2 * 2;
                b[0] = *(const unsigned*)bb;
                b[1] = *(const unsigned*)(bb + 16);
                MMA(cc[ks & 1], a, b);
            }
#pragma unroll
            for (int j = 0; j < 4; ++j) oo[j] = cc[0][j] + cc[1][j];
            klo = 2; nk = 3;
        }

        // out2_k = t_k * B2A^T : K=144 (t4 pre-scaled), dual accumulators
        for (int i = 0; i < nk; ++i) {
            const int k5 = klo + i;
            float cc[2][4] = {{0.f, 0.f, 0.f, 0.f}, {0.f, 0.f, 0.f, 0.f}};
            const int akc = (272 + 144 * k5) * 2;
#pragma unroll
            for (int ks = 0; ks < 9; ++ks) {
                const char* ab = Abase + akc + ks * 32;
                a[0] = *(const unsigned*)ab;
                a[1] = *(const unsigned*)(ab + 8 * AR);
                a[2] = *(const unsigned*)(ab + 16);
                a[3] = *(const unsigned*)(ab + 8 * AR + 16);
                const char* bb = sm + SB2A + (size_t)(nh * 8 + r0) * 304 + ks * 32 + c2 * 2;
                b[0] = *(const unsigned*)bb;
                b[1] = *(const unsigned*)(bb + 16);
                MMA(cc[ks & 1], a, b);
            }
#pragma unroll
            for (int j = 0; j < 4; ++j) r2[i][j] = cc[0][j] + cc[1][j];
        }

        __syncthreads();   // all A reads done; SA region becomes SO

        // write register results into SO (row stride SOR floats)
        float* so = (float*)(sm + SA);
        if (sel == 1) {
            float* d = so + (size_t)(mr + r0) * SOR + nh * 8 + c2;
            d[0] = oo[0]; d[1] = oo[1];
            float* d2 = d + 8 * SOR;
            d2[0] = oo[2]; d2[1] = oo[3];
        }
        for (int i = 0; i < nk; ++i) {
            const int k5 = klo + i;
            const int wc = nh * 8 + c2;
            float* d = so + (size_t)(mr + r0) * SOR + 64 + 5 * wc + k5;
            d[0] = r2[i][0]; d[5] = r2[i][1];
            float* d2 = d + 8 * SOR;
            d2[0] = r2[i][2]; d2[5] = r2[i][3];
        }
    }

    // ---- out1 scalar: 8 threads/node, thread q -> w = 2q..2q+1; write to SO ----
    {
        const int node = t >> 3, q = t & 7;
        const float4* xr = (const float4*)(sm + SX) + node * 16;
        const half* gr = (const half*)(sm + SG + (size_t)node * 528);
        float acc[6];
#pragma unroll
        for (int j = 0; j < 6; ++j) acc[j] = 0.f;
#pragma unroll 4
        for (int u = 0; u < 16; ++u) {
            float4 xv = xr[u];
            half2 g01 = *(const half2*)(gr + u * 16 + q * 2);
            float2 f01 = __half22float2(g01);
            acc[0] = fmaf(xv.y, f01.x, acc[0]);
            acc[1] = fmaf(xv.z, f01.x, acc[1]);
            acc[2] = fmaf(xv.w, f01.x, acc[2]);
            acc[3] = fmaf(xv.y, f01.y, acc[3]);
            acc[4] = fmaf(xv.z, f01.y, acc[4]);
            acc[5] = fmaf(xv.w, f01.y, acc[5]);
        }
        float* d = (float*)(sm + SA) + (size_t)node * SOR + 16 + 6 * q;
        d[0] = acc[0]; d[1] = acc[1]; d[2] = acc[2];
        d[3] = acc[3]; d[4] = acc[4]; d[5] = acc[5];
    }
    __syncthreads();

    // ---- coalesced flush: SO -> GMEM, float4 ----
    {
        const float* so = (const float*)(sm + SA);
        for (int i = t; i < NODES * 36; i += NT) {
            int node = i / 36, f = i % 36;
            if (nodeBase + node < nnodes) {
                float4 v = *(const float4*)(so + (size_t)node * SOR + f * 4);
                *(float4*)(out + (size_t)(nodeBase + node) * 144 + f * 4) = v;
            }
        }
    }
}

extern "C" void kernel_launch(void* const* d_in, const int* in_sizes, int n_in,
                              void* d_out, int out_size) {
    const float* nf   = (const float*)d_in[0];
    const float* nm   = (const float*)d_in[1];
    const float* w000 = (const float*)d_in[2];
    const float* w101 = (const float*)d_in[3];
    const float* w110 = (const float*)d_in[4];
    const float* w112 = (const float*)d_in[5];
    const int nnodes = in_sizes[0] / 64;

    prep_kernel<<<32, 256>>>(w000, w101, w110, w112);

    cudaFuncSetAttribute(tsq_kernel, cudaFuncAttributeMaxDynamicSharedMemorySize, SMEM_BYTES);
    const int grid = (nnodes + NODES - 1) / NODES;
    tsq_kernel<<<grid, NT, SMEM_BYTES>>>(nf, nm, (float*)d_out, nnodes);
}